// round 11
// baseline (speedup 1.0000x reference)
#include <cuda_runtime.h>
#include <cuda_fp16.h>
#include <cstdint>

#define N_USERS 100000
#define N_ITEMS 200000
#define N_NODES 300000   // N_USERS + N_ITEMS
#define DIM 64
#define N_EDGES 3200000
#define N_LAYERS 3

#define SCAN_T 512
#define N_SCAN_BLOCKS ((N_NODES + SCAN_T - 1) / SCAN_T)   // 586

// Half-precision ping-pong node buffers (38.4 MB each — L2-resident)
__device__ __half2 g_h0[(size_t)N_NODES * (DIM / 2)];
__device__ __half2 g_h1[(size_t)N_NODES * (DIM / 2)];

// CSR build scratch
__device__ int   g_counts[N_NODES];
__device__ int   g_rowptr[N_NODES + 1];
__device__ int   g_cursor[N_NODES];
__device__ int   g_chain[N_SCAN_BLOCKS];   // decoupled-lookback chain (-1 = not ready)
__device__ int   g_ticket;
__device__ __align__(16) int2 g_edges[N_EDGES];  // {col, bits(val)}; 16B-aligned for int4 pair loads

// ---------------------------------------------------------------------------
// Concat + fp16 snapshot + scratch init.
//   out <- concat(user,item) fp32 ; H0 <- same in half2
//   counts <- 0 ; chain <- -1 ; ticket <- 0     (runs before hist/scan)
// ---------------------------------------------------------------------------
__global__ void __launch_bounds__(256) concat_kernel(
    const float* __restrict__ user_emb, const float* __restrict__ item_emb,
    float* __restrict__ out, __half2* __restrict__ h)
{
    int i = blockIdx.x * blockDim.x + threadIdx.x;   // float2 index
    const int n2 = N_NODES * (DIM / 2);
    if (i < N_NODES) g_counts[i] = 0;
    if (i < N_SCAN_BLOCKS) g_chain[i] = -1;
    if (i == 0) g_ticket = 0;
    if (i >= n2) return;
    const int nu2 = N_USERS * (DIM / 2);
    float2 v = (i < nu2)
        ? reinterpret_cast<const float2*>(user_emb)[i]
        : reinterpret_cast<const float2*>(item_emb)[i - nu2];
    reinterpret_cast<float2*>(out)[i] = v;
    h[i] = __floats2half2_rn(v.x, v.y);
}

// ---------------------------------------------------------------------------
// CSR build: histogram of row ids
// ---------------------------------------------------------------------------
__global__ void __launch_bounds__(256) hist_kernel(const int* __restrict__ rows)
{
    int e = blockIdx.x * blockDim.x + threadIdx.x;
    if (e >= N_EDGES) return;
    atomicAdd(&g_counts[__ldg(&rows[e])], 1);
}

// ---------------------------------------------------------------------------
// Single-kernel exclusive scan (decoupled chain). 512 thr/block, 586 blocks —
// all co-resident at 4 blocks/SM, so the chain spin-wait cannot deadlock;
// ticket ordering decouples bid from scheduling order anyway.
// Writes rowptr[i], cursor[i], rowptr[N_NODES].
// ---------------------------------------------------------------------------
__global__ void __launch_bounds__(SCAN_T) scan_kernel()
{
    __shared__ int sh_warp[16];
    __shared__ int sh_bid;
    __shared__ int sh_prev;

    if (threadIdx.x == 0) sh_bid = atomicAdd(&g_ticket, 1);
    __syncthreads();
    int bid = sh_bid;
    int i = bid * SCAN_T + threadIdx.x;
    int v = (i < N_NODES) ? g_counts[i] : 0;

    int lane = threadIdx.x & 31;
    int wid  = threadIdx.x >> 5;

    // warp inclusive scan
    int s = v;
    #pragma unroll
    for (int o = 1; o < 32; o <<= 1) {
        int t = __shfl_up_sync(0xFFFFFFFFu, s, o);
        if (lane >= o) s += t;
    }
    if (lane == 31) sh_warp[wid] = s;
    __syncthreads();
    if (wid == 0) {
        int w = (lane < 16) ? sh_warp[lane] : 0;
        #pragma unroll
        for (int o = 1; o < 16; o <<= 1) {
            int t = __shfl_up_sync(0xFFFFFFFFu, w, o);
            if (lane >= o) w += t;
        }
        if (lane < 16) sh_warp[lane] = w;
    }
    __syncthreads();
    int blockIncl  = s + (wid ? sh_warp[wid - 1] : 0);
    int blockTotal = sh_warp[15];

    if (threadIdx.x == 0) {
        int prev = 0;
        if (bid > 0) {
            while ((prev = *(volatile int*)&g_chain[bid - 1]) < 0) {}
        }
        sh_prev = prev;
        __threadfence();
        *(volatile int*)&g_chain[bid] = prev + blockTotal;
    }
    __syncthreads();

    int excl = sh_prev + blockIncl - v;
    if (i < N_NODES) { g_rowptr[i] = excl; g_cursor[i] = excl; }
    if (i == 0) g_rowptr[N_NODES] = N_EDGES;
}

// ---------------------------------------------------------------------------
// CSR build: scatter edges (packed {col,val}) into row-sorted order
// ---------------------------------------------------------------------------
__global__ void __launch_bounds__(256) edge_scatter_kernel(
    const int* __restrict__ rows, const int* __restrict__ cols,
    const float* __restrict__ vals)
{
    int e = blockIdx.x * blockDim.x + threadIdx.x;
    if (e >= N_EDGES) return;
    int r = __ldg(&rows[e]);
    int pos = atomicAdd(&g_cursor[r], 1);
    int2 cv;
    cv.x = __ldg(&cols[e]);
    cv.y = __float_as_int(__ldg(&vals[e]));
    g_edges[pos] = cv;
}

// ---------------------------------------------------------------------------
// CSR SpMM (half2 gather, fp32 accumulate) with fused accumulate epilogue.
// One warp per row, one half2 (2 dims) per lane.
// Edge metadata read as int4 PAIRS (2 edges / 16B load) — 1.5 warp-LDGs per
// edge instead of 2, attacking the LSU-issue floor.
// ---------------------------------------------------------------------------
__global__ void __launch_bounds__(256) spmm_csr_fused(
    const __half2* __restrict__ xh, __half2* __restrict__ yh,
    float* __restrict__ out, float scale, int writeY)
{
    int warp = (blockIdx.x * blockDim.x + threadIdx.x) >> 5;
    if (warp >= N_NODES) return;
    int lane = threadIdx.x & 31;

    int beg = __ldg(&g_rowptr[warp]);
    int end = __ldg(&g_rowptr[warp + 1]);

    float sx = 0.f, sy = 0.f;
    int j = beg;

    // align j to even for int4 pair loads
    if ((j & 1) && j < end) {
        int2 cv = __ldg(&g_edges[j]);
        __half2 xv = __ldg(xh + (((long long)cv.x << 5) + lane));
        float v = __int_as_float(cv.y);
        float2 xf = __half22float2(xv);
        sx += v * xf.x; sy += v * xf.y;
        ++j;
    }

    for (; j + 4 <= end; j += 4) {
        const int4* p = reinterpret_cast<const int4*>(&g_edges[j]);
        int4 a = __ldg(p);       // edges j, j+1
        int4 b = __ldg(p + 1);   // edges j+2, j+3
        __half2 x0 = __ldg(xh + (((long long)a.x << 5) + lane));
        __half2 x1 = __ldg(xh + (((long long)a.z << 5) + lane));
        __half2 x2 = __ldg(xh + (((long long)b.x << 5) + lane));
        __half2 x3 = __ldg(xh + (((long long)b.z << 5) + lane));
        float v0 = __int_as_float(a.y);
        float v1 = __int_as_float(a.w);
        float v2 = __int_as_float(b.y);
        float v3 = __int_as_float(b.w);
        float2 f0 = __half22float2(x0);
        float2 f1 = __half22float2(x1);
        float2 f2 = __half22float2(x2);
        float2 f3 = __half22float2(x3);
        sx += v0 * f0.x + v1 * f1.x + v2 * f2.x + v3 * f3.x;
        sy += v0 * f0.y + v1 * f1.y + v2 * f2.y + v3 * f3.y;
    }
    if (j + 2 <= end) {
        const int4* p = reinterpret_cast<const int4*>(&g_edges[j]);
        int4 a = __ldg(p);
        __half2 x0 = __ldg(xh + (((long long)a.x << 5) + lane));
        __half2 x1 = __ldg(xh + (((long long)a.z << 5) + lane));
        float v0 = __int_as_float(a.y);
        float v1 = __int_as_float(a.w);
        float2 f0 = __half22float2(x0);
        float2 f1 = __half22float2(x1);
        sx += v0 * f0.x + v1 * f1.x;
        sy += v0 * f0.y + v1 * f1.y;
        j += 2;
    }
    if (j < end) {
        int2 cv = __ldg(&g_edges[j]);
        __half2 xv = __ldg(xh + (((long long)cv.x << 5) + lane));
        float v = __int_as_float(cv.y);
        float2 xf = __half22float2(xv);
        sx += v * xf.x; sy += v * xf.y;
    }

    long long o = ((long long)warp << 5) + lane;
    if (writeY) yh[o] = __floats2half2_rn(sx, sy);

    float2 b2 = reinterpret_cast<float2*>(out)[o];
    float2 r;
    r.x = (b2.x + sx) * scale;
    r.y = (b2.y + sy) * scale;
    reinterpret_cast<float2*>(out)[o] = r;
}

extern "C" void kernel_launch(void* const* d_in, const int* in_sizes, int n_in,
                              void* d_out, int out_size)
{
    const float* user_emb = (const float*)d_in[0];
    const float* item_emb = (const float*)d_in[1];
    const int*   rows     = (const int*)d_in[2];
    const int*   cols     = (const int*)d_in[3];
    const float* vals     = (const float*)d_in[4];
    // d_in[5] = n_layers, fixed at 3 (compiled in as N_LAYERS)
    (void)in_sizes; (void)n_in; (void)out_size;

    float* out = (float*)d_out;

    __half2 *H0, *H1;
    cudaGetSymbolAddress((void**)&H0, g_h0);
    cudaGetSymbolAddress((void**)&H1, g_h1);

    // 1. concat + scratch init (zeroes counts/chain/ticket)
    {
        const int n2 = N_NODES * (DIM / 2);
        const int t = 256, b = (n2 + t - 1) / t;
        concat_kernel<<<b, t>>>(user_emb, item_emb, out, H0);
    }
    // 2. histogram
    {
        const int t = 256, b = (N_EDGES + t - 1) / t;
        hist_kernel<<<b, t>>>(rows);
    }
    // 3. single-kernel scan -> rowptr, cursor
    scan_kernel<<<N_SCAN_BLOCKS, SCAN_T>>>();
    // 4. edge scatter -> packed CSR
    {
        const int t = 256, b = (N_EDGES + t - 1) / t;
        edge_scatter_kernel<<<b, t>>>(rows, cols, vals);
    }

    const int spmm_threads = 256;
    const long long spmm_total = (long long)N_NODES * 32;
    const int spmm_blocks = (int)((spmm_total + spmm_threads - 1) / spmm_threads);

    // 5-7. three fused layers
    spmm_csr_fused<<<spmm_blocks, spmm_threads>>>(H0, H1, out, 1.0f, 1);
    spmm_csr_fused<<<spmm_blocks, spmm_threads>>>(H1, H0, out, 1.0f, 1);
    spmm_csr_fused<<<spmm_blocks, spmm_threads>>>(H0, nullptr, out, 0.25f, 0);
}